// round 1
// baseline (speedup 1.0000x reference)
#include <cuda_runtime.h>
#include <cstdint>

#define THREADS 256
#define KDIM 120
#define INP 512
#define NPAIR 13          // 26 padded columns as 13 f32x2 pairs (25 real)
#define KC 24             // k-chunk (96B per row = 3 aligned sectors)
#define NCHUNK 5
#define XT_STRIDE 514     // even (LDS.64-aligned), low-conflict

#define SW_FLOATS (KDIM * NPAIR * 2)            // 3120
#define U_OFF SW_FLOATS
#define SX_FLOATS (KC * XT_STRIDE)              // 12336
#define SCR_STRIDE 27
#define RED_OFF (U_OFF + THREADS * SCR_STRIDE)  // 10032
#define RAW_OFF (RED_OFF + 8 * 26)              // 10240
#define OUT_OFF (RAW_OFF + 32)                  // 10272
#define SMEM_FLOATS (U_OFF + SX_FLOATS)         // 15456
#define SMEM_BYTES (SMEM_FLOATS * 4)            // 61824

__device__ __forceinline__ unsigned long long dup2(float v) {
    unsigned long long r;
    asm("mov.b64 %0, {%1, %1};" : "=l"(r) : "r"(__float_as_uint(v)));
    return r;
}
__device__ __forceinline__ void ffma2(unsigned long long& d, unsigned long long a, unsigned long long b) {
    asm("fma.rn.f32x2 %0, %1, %2, %0;" : "+l"(d) : "l"(a), "l"(b));
}
__device__ __forceinline__ void unpack2(unsigned long long v, float& lo, float& hi) {
    unsigned int a, b2;
    asm("mov.b64 {%0, %1}, %2;" : "=r"(a), "=r"(b2) : "l"(v));
    lo = __uint_as_float(a);
    hi = __uint_as_float(b2);
}

extern __shared__ float smem[];

__global__ void __launch_bounds__(THREADS)
caps_kernel(const float* __restrict__ x, const float* __restrict__ W, float* __restrict__ out)
{
    const int b = blockIdx.x;
    const int t = threadIdx.x;

    float* sW      = smem;            // [120][13] float2, pad col 25 = 0
    float* sX      = smem + U_OFF;    // transposed x chunk [KC][XT_STRIDE]
    float* scratch = smem + U_OFF;    // routing partials (aliases sX)
    float* red     = smem + RED_OFF;  // [8][26]
    float* raw     = smem + RAW_OFF;  // [25]
    float* sOut    = smem + OUT_OFF;  // [25]

    // ---- load W as duplicate-ready pairs (col 25 zero-padded) ----
    for (int idx = t; idx < KDIM * NPAIR; idx += THREADS) {
        int j = idx / NPAIR, p = idx % NPAIR;
        int c0 = 2 * p;
        float w0 = W[j * 25 + c0];
        float w1 = (c0 + 1 < 25) ? W[j * 25 + c0 + 1] : 0.f;
        sW[idx * 2 + 0] = w0;
        sW[idx * 2 + 1] = w1;
    }

    // ---- GEMM: u_hat[2 rows][26 cols] accumulated in 26 f32x2 registers ----
    unsigned long long acc[2][NPAIR];
    #pragma unroll
    for (int r = 0; r < 2; r++)
        #pragma unroll
        for (int p = 0; p < NPAIR; p++) acc[r][p] = 0ull;

    const float4* xg = reinterpret_cast<const float4*>(x) + (size_t)b * (INP * KDIM / 4);
    const int r2 = 2 * t;

    for (int kc = 0; kc < NCHUNK; kc++) {
        __syncthreads();                 // sX safe to overwrite (also covers sW on first pass)
        const int k0q = kc * (KC / 4);
        #pragma unroll
        for (int it2 = 0; it2 < (INP * KC / 4) / THREADS; it2++) {   // 12 float4 per thread
            int idx = t + it2 * THREADS;
            int row = idx / (KC / 4);
            int slot = idx % (KC / 4);
            float4 v = xg[row * (KDIM / 4) + k0q + slot];
            int jj = slot * 4;
            sX[(jj + 0) * XT_STRIDE + row] = v.x;
            sX[(jj + 1) * XT_STRIDE + row] = v.y;
            sX[(jj + 2) * XT_STRIDE + row] = v.z;
            sX[(jj + 3) * XT_STRIDE + row] = v.w;
        }
        __syncthreads();
        const unsigned long long* sWq =
            reinterpret_cast<const unsigned long long*>(sW) + kc * KC * NPAIR;
        #pragma unroll 4
        for (int j = 0; j < KC; j++) {
            float2 xv = *reinterpret_cast<const float2*>(sX + j * XT_STRIDE + r2);
            unsigned long long a0 = dup2(xv.x);
            unsigned long long a1 = dup2(xv.y);
            #pragma unroll
            for (int p = 0; p < NPAIR; p++) {
                unsigned long long wp = sWq[j * NPAIR + p];   // warp-uniform -> LDS broadcast
                ffma2(acc[0][p], a0, wp);
                ffma2(acc[1][p], a1, wp);
            }
        }
    }
    __syncthreads();

    // ---- unpack u_hat to scalar regs ----
    float u[2][26];
    #pragma unroll
    for (int r = 0; r < 2; r++)
        #pragma unroll
        for (int p = 0; p < NPAIR; p++)
            unpack2(acc[r][p], u[r][2 * p], u[r][2 * p + 1]);

    float bb[2][5];
    #pragma unroll
    for (int r = 0; r < 2; r++)
        #pragma unroll
        for (int i = 0; i < 5; i++) bb[r][i] = 0.f;

    const int lane = t & 31, g = t >> 5;

    // ---- 4 routing iterations ----
    for (int it = 0; it < 4; it++) {
        // softmax over 5 capsules, per owned row
        float cw[2][5];
        #pragma unroll
        for (int r = 0; r < 2; r++) {
            float m = bb[r][0];
            #pragma unroll
            for (int i = 1; i < 5; i++) m = fmaxf(m, bb[r][i]);
            float e[5], s = 0.f;
            #pragma unroll
            for (int i = 0; i < 5; i++) { e[i] = __expf(bb[r][i] - m); s += e[i]; }
            float inv = 1.f / s;
            #pragma unroll
            for (int i = 0; i < 5; i++) cw[r][i] = e[i] * inv;
        }
        // per-thread partial of sum_j c[i][j] * u_hat[j][i][k]
        #pragma unroll
        for (int c = 0; c < 25; c++)
            scratch[t * SCR_STRIDE + c] = cw[0][c / 5] * u[0][c] + cw[1][c / 5] * u[1][c];
        __syncthreads();
        // warp-group reduce (each warp sums its 32 threads, per column)
        if (lane < 25) {
            float s = 0.f;
            #pragma unroll
            for (int uu = 0; uu < 32; uu++) s += scratch[(g * 32 + uu) * SCR_STRIDE + lane];
            red[g * 26 + lane] = s;
        }
        __syncthreads();
        if (t < 25) {
            float s = 0.f;
            #pragma unroll
            for (int gg = 0; gg < 8; gg++) s += red[gg * 26 + t];
            raw[t] = s;
        }
        __syncthreads();
        if (t < 25) {
            int i5 = (t / 5) * 5;
            float sq = 0.f;
            #pragma unroll
            for (int k = 0; k < 5; k++) { float v = raw[i5 + k]; sq += v * v; }
            sOut[t] = raw[t] * rsqrtf(sq + 1e-7f);   // squash = pure norm-normalization
        }
        __syncthreads();
        if (it < 3) {
            // b REPLACED (reference: b = einsum(...)), not accumulated
            float ov[25];
            #pragma unroll
            for (int c = 0; c < 25; c++) ov[c] = sOut[c];
            #pragma unroll
            for (int r = 0; r < 2; r++)
                #pragma unroll
                for (int i = 0; i < 5; i++) {
                    float s = 0.f;
                    #pragma unroll
                    for (int k = 0; k < 5; k++) s += ov[i * 5 + k] * u[r][i * 5 + k];
                    bb[r][i] = s;
                }
        }
    }

    if (t < 25) out[b * 25 + t] = sOut[t];
}

extern "C" void kernel_launch(void* const* d_in, const int* in_sizes, int n_in,
                              void* d_out, int out_size)
{
    const float* x = (const float*)d_in[0];
    const float* W = (const float*)d_in[1];
    float* out = (float*)d_out;
    cudaFuncSetAttribute(caps_kernel, cudaFuncAttributeMaxDynamicSharedMemorySize, SMEM_BYTES);
    caps_kernel<<<1024, THREADS, SMEM_BYTES>>>(x, W, out);
}

// round 2
// speedup vs baseline: 1.0349x; 1.0349x over previous
#include <cuda_runtime.h>
#include <cstdint>

#define THREADS 256
#define KDIM 120
#define INP 512
#define NPAIR 13          // 13 f32x2 pairs = 26 cols (25 real + 1 zero pad)
#define WROW 28           // W row padded to 28 floats (112B, 16B-aligned)
#define KC 24             // k-chunk
#define NCHUNK 5
#define NJ2 (KC / 2)      // 12 float4 k-pair slots per chunk
#define X_STRIDE 1028     // floats between j2 slots (1028*4B; mod 128B = 16B -> bank-shifted)

#define SW_FLOATS (KDIM * WROW)                 // 3360
#define U_OFF SW_FLOATS
#define SX_FLOATS (NJ2 * X_STRIDE)              // 12336
#define SCR_STRIDE 27
#define RED_OFF (U_OFF + THREADS * SCR_STRIDE)
#define RAW_OFF (RED_OFF + 8 * 26)
#define OUT_OFF (RAW_OFF + 32)
#define SMEM_FLOATS (U_OFF + SX_FLOATS)         // 15696
#define SMEM_BYTES (SMEM_FLOATS * 4)            // 62784

typedef unsigned long long ull;

__device__ __forceinline__ ull dup2(float v) {
    ull r;
    asm("mov.b64 %0, {%1, %1};" : "=l"(r) : "r"(__float_as_uint(v)));
    return r;
}
__device__ __forceinline__ void ffma2(ull& d, ull a, ull b) {
    asm("fma.rn.f32x2 %0, %1, %2, %0;" : "+l"(d) : "l"(a), "l"(b));
}
__device__ __forceinline__ void unpack2(ull v, float& lo, float& hi) {
    unsigned int a, b2;
    asm("mov.b64 {%0, %1}, %2;" : "=r"(a), "=r"(b2) : "l"(v));
    lo = __uint_as_float(a);
    hi = __uint_as_float(b2);
}

extern __shared__ float smem[];

__global__ void __launch_bounds__(THREADS)
caps_kernel(const float* __restrict__ x, const float* __restrict__ W, float* __restrict__ out)
{
    const int b = blockIdx.x;
    const int t = threadIdx.x;

    float* sW      = smem;            // [120][28]: pairs 0..12 real (col25=0), 26..27 unused
    float* sX      = smem + U_OFF;    // [NJ2][X_STRIDE]: float4 per thread-rowpair
    float* scratch = smem + U_OFF;    // routing partials (aliases sX)
    float* red     = smem + RED_OFF;  // [8][26]
    float* raw     = smem + RAW_OFF;  // [25]
    float* sOut    = smem + OUT_OFF;  // [25]

    // ---- stage W: row-padded pairs, col 25 zeroed ----
    for (int idx = t; idx < KDIM * NPAIR; idx += THREADS) {
        int j = idx / NPAIR, p = idx % NPAIR;
        int c0 = 2 * p;
        sW[j * WROW + c0]     = W[j * 25 + c0];
        sW[j * WROW + c0 + 1] = (c0 + 1 < 25) ? W[j * 25 + c0 + 1] : 0.f;
    }

    // ---- GEMM: u_hat[2 rows][26 cols] in 26 f32x2 accumulators ----
    ull acc[2][NPAIR];
    #pragma unroll
    for (int r = 0; r < 2; r++)
        #pragma unroll
        for (int p = 0; p < NPAIR; p++) acc[r][p] = 0ull;

    const float4* xg = reinterpret_cast<const float4*>(x) + (size_t)b * (INP * KDIM / 4);

    for (int kc = 0; kc < NCHUNK; kc++) {
        __syncthreads();                 // sX safe to overwrite (first pass: sW visible too)
        const int k0q = kc * (KC / 4);
        #pragma unroll
        for (int it2 = 0; it2 < (INP * (KC / 4)) / THREADS; it2++) {   // 12 float4/thread
            int idx  = t + it2 * THREADS;
            int row  = idx / (KC / 4);
            int slot = idx % (KC / 4);
            float4 v = xg[row * (KDIM / 4) + k0q + slot];
            // float4 covers k-pairs j2=2*slot and 2*slot+1 for this row
            float* p0 = sX + (2 * slot) * X_STRIDE + (row >> 1) * 4 + (row & 1) * 2;
            *reinterpret_cast<float2*>(p0)            = make_float2(v.x, v.y);
            *reinterpret_cast<float2*>(p0 + X_STRIDE) = make_float2(v.z, v.w);
        }
        __syncthreads();

        #pragma unroll
        for (int j2 = 0; j2 < NJ2; j2++) {
            // {x(k0,r0), x(k1,r0), x(k0,r1), x(k1,r1)}
            float4 xv = *reinterpret_cast<const float4*>(sX + j2 * X_STRIDE + t * 4);
            ull a00 = dup2(xv.x);   // k0, row0
            ull a10 = dup2(xv.y);   // k1, row0
            ull a01 = dup2(xv.z);   // k0, row1
            ull a11 = dup2(xv.w);   // k1, row1

            const float* wr = sW + (kc * KC + 2 * j2) * WROW;
            // k0
            #pragma unroll
            for (int m = 0; m < 6; m++) {
                ulonglong2 w = *reinterpret_cast<const ulonglong2*>(wr + m * 4);
                ffma2(acc[0][2 * m],     a00, w.x);
                ffma2(acc[1][2 * m],     a01, w.x);
                ffma2(acc[0][2 * m + 1], a00, w.y);
                ffma2(acc[1][2 * m + 1], a01, w.y);
            }
            {
                ull w12 = *reinterpret_cast<const ull*>(wr + 24);
                ffma2(acc[0][12], a00, w12);
                ffma2(acc[1][12], a01, w12);
            }
            // k1
            #pragma unroll
            for (int m = 0; m < 6; m++) {
                ulonglong2 w = *reinterpret_cast<const ulonglong2*>(wr + WROW + m * 4);
                ffma2(acc[0][2 * m],     a10, w.x);
                ffma2(acc[1][2 * m],     a11, w.x);
                ffma2(acc[0][2 * m + 1], a10, w.y);
                ffma2(acc[1][2 * m + 1], a11, w.y);
            }
            {
                ull w12 = *reinterpret_cast<const ull*>(wr + WROW + 24);
                ffma2(acc[0][12], a10, w12);
                ffma2(acc[1][12], a11, w12);
            }
        }
    }
    __syncthreads();

    // ---- unpack u_hat ----
    float u[2][26];
    #pragma unroll
    for (int r = 0; r < 2; r++)
        #pragma unroll
        for (int p = 0; p < NPAIR; p++)
            unpack2(acc[r][p], u[r][2 * p], u[r][2 * p + 1]);

    float bb[2][5];
    #pragma unroll
    for (int r = 0; r < 2; r++)
        #pragma unroll
        for (int i = 0; i < 5; i++) bb[r][i] = 0.f;

    const int lane = t & 31, g = t >> 5;

    // ---- 4 routing iterations ----
    for (int it = 0; it < 4; it++) {
        float cw[2][5];
        #pragma unroll
        for (int r = 0; r < 2; r++) {
            float m = bb[r][0];
            #pragma unroll
            for (int i = 1; i < 5; i++) m = fmaxf(m, bb[r][i]);
            float e[5], s = 0.f;
            #pragma unroll
            for (int i = 0; i < 5; i++) { e[i] = __expf(bb[r][i] - m); s += e[i]; }
            float inv = 1.f / s;
            #pragma unroll
            for (int i = 0; i < 5; i++) cw[r][i] = e[i] * inv;
        }
        #pragma unroll
        for (int c = 0; c < 25; c++)
            scratch[t * SCR_STRIDE + c] = cw[0][c / 5] * u[0][c] + cw[1][c / 5] * u[1][c];
        __syncthreads();
        if (lane < 25) {
            float s = 0.f;
            #pragma unroll
            for (int uu = 0; uu < 32; uu++) s += scratch[(g * 32 + uu) * SCR_STRIDE + lane];
            red[g * 26 + lane] = s;
        }
        __syncthreads();
        if (t < 25) {
            float s = 0.f;
            #pragma unroll
            for (int gg = 0; gg < 8; gg++) s += red[gg * 26 + t];
            raw[t] = s;
        }
        __syncthreads();
        if (t < 25) {
            int i5 = (t / 5) * 5;
            float sq = 0.f;
            #pragma unroll
            for (int k = 0; k < 5; k++) { float v = raw[i5 + k]; sq += v * v; }
            sOut[t] = raw[t] * rsqrtf(sq + 1e-7f);
        }
        __syncthreads();
        if (it < 3) {
            float ov[25];
            #pragma unroll
            for (int c = 0; c < 25; c++) ov[c] = sOut[c];
            #pragma unroll
            for (int r = 0; r < 2; r++)
                #pragma unroll
                for (int i = 0; i < 5; i++) {
                    float s = 0.f;
                    #pragma unroll
                    for (int k = 0; k < 5; k++) s += ov[i * 5 + k] * u[r][i * 5 + k];
                    bb[r][i] = s;   // b REPLACED each iteration (matches reference)
                }
        }
    }

    if (t < 25) out[b * 25 + t] = sOut[t];
}

extern "C" void kernel_launch(void* const* d_in, const int* in_sizes, int n_in,
                              void* d_out, int out_size)
{
    const float* x = (const float*)d_in[0];
    const float* W = (const float*)d_in[1];
    float* out = (float*)d_out;
    cudaFuncSetAttribute(caps_kernel, cudaFuncAttributeMaxDynamicSharedMemorySize, SMEM_BYTES);
    caps_kernel<<<1024, THREADS, SMEM_BYTES>>>(x, W, out);
}